// round 2
// baseline (speedup 1.0000x reference)
#include <cuda_runtime.h>

// Problem constants
#define B_    256
#define T_    512
#define D_    64
#define H_    512
#define G_    2048          // 4*H
#define NCTA  128
#define NTHR  256
#define CPC   16            // gate columns per CTA (4 h-cols * 4 gates)
#define HCOLS 4             // h columns per CTA

// Persistent state / scratch (no cudaMalloc allowed).
// hT is transposed: hT[buf][k][b], double buffered, padded by 8 rows so the
// software-pipelined prefetch can read one block past the end safely.
__device__ float    g_hT[2 * H_ * B_ + 8 * B_];
__device__ unsigned g_count;
__device__ unsigned g_gen;

// ---------------- math helpers ----------------
__device__ __forceinline__ float softplus_(float r) {
    return (r > 15.f) ? r : log1pf(expf(r));
}
__device__ __forceinline__ float sample_(float mu, float rho, float eps) {
    return mu + softplus_(rho) * eps;
}
// fast sigmoid / tanh via EX2-based __expf (rel err ~1e-6, fine for 1e-3 tol)
__device__ __forceinline__ float sigmoid_(float x) {
    return __fdividef(1.f, 1.f + __expf(-x));
}
__device__ __forceinline__ float tanh_(float x) {
    return __fdividef(2.f, 1.f + __expf(-2.f * x)) - 1.f;
}

// ---------------- packed fp32x2 FMA (sm_100+ only) ----------------
__device__ __forceinline__ unsigned long long pack2_(float x, float y) {
    unsigned long long r;
    asm("mov.b64 %0, {%1, %2};" : "=l"(r) : "f"(x), "f"(y));
    return r;
}
__device__ __forceinline__ void unpack2_(unsigned long long v, float& x, float& y) {
    asm("mov.b64 {%0, %1}, %2;" : "=f"(x), "=f"(y) : "l"(v));
}
__device__ __forceinline__ void ffma2_(unsigned long long& acc,
                                       unsigned long long a,
                                       unsigned long long b) {
    asm("fma.rn.f32x2 %0, %1, %2, %3;" : "=l"(acc) : "l"(a), "l"(b), "l"(acc));
}

// ---------------- grid barrier (sense via monotonically increasing epoch) ---
__device__ __forceinline__ void grid_sync(unsigned target) {
    __syncthreads();
    if (threadIdx.x == 0) {
        __threadfence();
        unsigned t = atomicAdd(&g_count, 1u);
        if (t == NCTA - 1) {
            g_count = 0;
            __threadfence();
            atomicExch(&g_gen, target);
        } else {
            while (atomicAdd(&g_gen, 0u) < target) { __nanosleep(20); }
            __threadfence();
        }
    }
    __syncthreads();
}

extern "C" __global__ void bar_init_kernel() {
    g_count = 0;
    g_gen = 0;
}

// ---------------- main persistent LSTM kernel ----------------
extern "C" __global__ void __launch_bounds__(NTHR, 1)
lstm_persistent(const float* __restrict__ x,
                const float* __restrict__ wih_mu, const float* __restrict__ wih_rho,
                const float* __restrict__ wih_eps,
                const float* __restrict__ whh_mu, const float* __restrict__ whh_rho,
                const float* __restrict__ whh_eps,
                const float* __restrict__ b_mu,   const float* __restrict__ b_rho,
                const float* __restrict__ b_eps,
                const float* __restrict__ lin_w,  const float* __restrict__ lin_b,
                float* __restrict__ out)
{
    __shared__ float w_hh_s[H_ * CPC];   // 32 KB, [k][16]
    __shared__ float w_ih_s[D_ * CPC];   //  4 KB, [d][16]
    __shared__ float bias_s[CPC];

    const int tid = threadIdx.x;
    const int cta = blockIdx.x;
    const int j0  = cta * HCOLS;         // first h-column owned by this CTA
    const int b   = tid;                 // thread owns one batch row

    // ---- sample weights for our 16 gate columns straight into SMEM ----
    for (int idx = tid; idx < H_ * CPC; idx += NTHR) {
        int k = idx >> 4, cc = idx & 15;
        int col = (cc >> 2) * H_ + j0 + (cc & 3);
        int gi = k * G_ + col;
        w_hh_s[idx] = sample_(whh_mu[gi], whh_rho[gi], whh_eps[gi]);
    }
    for (int idx = tid; idx < D_ * CPC; idx += NTHR) {
        int d = idx >> 4, cc = idx & 15;
        int col = (cc >> 2) * H_ + j0 + (cc & 3);
        int gi = d * G_ + col;
        w_ih_s[idx] = sample_(wih_mu[gi], wih_rho[gi], wih_eps[gi]);
    }
    if (tid < CPC) {
        int col = (tid >> 2) * H_ + j0 + (tid & 3);
        bias_s[tid] = sample_(b_mu[col], b_rho[col], b_eps[col]);
    }
    // zero h buffer 0 for our columns (c state lives in registers)
    #pragma unroll
    for (int jj = 0; jj < HCOLS; jj++)
        g_hT[(j0 + jj) * B_ + b] = 0.f;

    float creg[HCOLS] = {0.f, 0.f, 0.f, 0.f};

    grid_sync(1);
    __syncthreads();

    // hoist bias pairs into registers
    unsigned long long bias2[8];
    #pragma unroll
    for (int p = 0; p < 8; p++) bias2[p] = pack2_(bias_s[2 * p], bias_s[2 * p + 1]);

    unsigned sync_t = 2;

    #pragma unroll 1
    for (int t = 0; t < T_; t++) {
        const int cur = t & 1, nxt = cur ^ 1;

        unsigned long long acc[8];
        #pragma unroll
        for (int p = 0; p < 8; p++) acc[p] = bias2[p];

        // ---- x[b, t, :] contribution (contiguous 256B per thread) ----
        const float4* xrow = (const float4*)(x + (size_t)b * (T_ * D_) + (size_t)t * D_);
        #pragma unroll 4
        for (int d4 = 0; d4 < D_ / 4; d4++) {
            float4 xq = xrow[d4];
            float xv[4] = {xq.x, xq.y, xq.z, xq.w};
            #pragma unroll
            for (int u = 0; u < 4; u++) {
                unsigned long long xv2 = pack2_(xv[u], xv[u]);
                const ulonglong2* wr =
                    (const ulonglong2*)&w_ih_s[(d4 * 4 + u) * CPC];
                ulonglong2 w0 = wr[0], w1 = wr[1], w2 = wr[2], w3 = wr[3];
                ffma2_(acc[0], w0.x, xv2); ffma2_(acc[1], w0.y, xv2);
                ffma2_(acc[2], w1.x, xv2); ffma2_(acc[3], w1.y, xv2);
                ffma2_(acc[4], w2.x, xv2); ffma2_(acc[5], w2.y, xv2);
                ffma2_(acc[6], w3.x, xv2); ffma2_(acc[7], w3.y, xv2);
            }
        }

        // ---- h @ w_hh contribution, software-pipelined, .cg loads (L1 is
        //      not coherent with other SMs' writes between steps) ----
        const float* hbase = g_hT + cur * (H_ * B_) + b;
        float hv[8], hn[8];
        #pragma unroll
        for (int u = 0; u < 8; u++) hv[u] = __ldcg(&hbase[u * B_]);

        #pragma unroll 1
        for (int k = 0; k < H_; k += 8) {
            const float* nb = hbase + (k + 8) * B_;  // padded: safe at k=504
            #pragma unroll
            for (int u = 0; u < 8; u++) hn[u] = __ldcg(&nb[u * B_]);
            #pragma unroll
            for (int u = 0; u < 8; u++) {
                unsigned long long hv2 = pack2_(hv[u], hv[u]);
                const ulonglong2* wr =
                    (const ulonglong2*)&w_hh_s[(k + u) * CPC];
                ulonglong2 w0 = wr[0], w1 = wr[1], w2 = wr[2], w3 = wr[3];
                ffma2_(acc[0], w0.x, hv2); ffma2_(acc[1], w0.y, hv2);
                ffma2_(acc[2], w1.x, hv2); ffma2_(acc[3], w1.y, hv2);
                ffma2_(acc[4], w2.x, hv2); ffma2_(acc[5], w2.y, hv2);
                ffma2_(acc[6], w3.x, hv2); ffma2_(acc[7], w3.y, hv2);
            }
            #pragma unroll
            for (int u = 0; u < 8; u++) hv[u] = hn[u];
        }

        // ---- gates / state update / write h_{t+1} ----
        float ga[16];
        #pragma unroll
        for (int p = 0; p < 8; p++) unpack2_(acc[p], ga[2 * p], ga[2 * p + 1]);

        float* hout = g_hT + nxt * (H_ * B_);
        #pragma unroll
        for (int jj = 0; jj < HCOLS; jj++) {
            float iv = sigmoid_(ga[jj]);
            float fv = sigmoid_(ga[4 + jj]);
            float gv = tanh_(ga[8 + jj]);
            float ov = sigmoid_(ga[12 + jj]);
            creg[jj] = fv * creg[jj] + iv * gv;
            float hval = ov * tanh_(creg[jj]);
            __stcg(&hout[(j0 + jj) * B_ + b], hval);
        }

        grid_sync(sync_t++);
    }

    // After t=511 (cur=1), h_last sits in buffer 0.
    if (cta == 0) {
        float s = 0.f;
        #pragma unroll 4
        for (int j = 0; j < H_; j++)
            s += __ldcg(&g_hT[j * B_ + b]) * __ldg(&lin_w[j]);
        out[b] = s + __ldg(&lin_b[0]);
    }
}

// ---------------- launch ----------------
extern "C" void kernel_launch(void* const* d_in, const int* in_sizes, int n_in,
                              void* d_out, int out_size)
{
    const float* x       = (const float*)d_in[0];
    const float* wih_mu  = (const float*)d_in[1];
    const float* wih_rho = (const float*)d_in[2];
    const float* wih_eps = (const float*)d_in[3];
    const float* whh_mu  = (const float*)d_in[4];
    const float* whh_rho = (const float*)d_in[5];
    const float* whh_eps = (const float*)d_in[6];
    const float* b_mu    = (const float*)d_in[7];
    const float* b_rho   = (const float*)d_in[8];
    const float* b_eps   = (const float*)d_in[9];
    const float* lin_w   = (const float*)d_in[10];
    const float* lin_b   = (const float*)d_in[11];
    float* out = (float*)d_out;

    bar_init_kernel<<<1, 1>>>();
    lstm_persistent<<<NCTA, NTHR>>>(x,
                                    wih_mu, wih_rho, wih_eps,
                                    whh_mu, whh_rho, whh_eps,
                                    b_mu, b_rho, b_eps,
                                    lin_w, lin_b, out);
}

// round 3
// speedup vs baseline: 1.1508x; 1.1508x over previous
#include <cuda_runtime.h>

// Problem constants
#define B_    256
#define T_    512
#define D_    64
#define H_    512
#define G_    2048          // 4*H
#define NCTA  128
#define NTHR  512
#define CPC   16            // gate columns per CTA (4 h-cols * 4 gates)
#define HCOLS 4             // h columns per CTA
#define KHALF 256           // k range per thread-half

// Dynamic SMEM layout (in floats)
#define WHH_OFF  0                      // [512][16]  = 8192
#define WIH_OFF  8192                   // [64][16]   = 1024
#define BIAS_OFF 9216                   // 16 (pad 32)
#define PART_OFF 9248                   // [256][20]  = 5120 (80B rows, conflict-free)
#define PART_STRIDE 20
#define SMEM_FLOATS (PART_OFF + 256 * PART_STRIDE)
#define SMEM_BYTES  (SMEM_FLOATS * 4)

// Persistent state / scratch (no cudaMalloc allowed).
// hT transposed: hT[buf][k][b], double buffered, padded 8 rows for prefetch.
__device__ float    g_hT[2 * H_ * B_ + 8 * B_];
__device__ unsigned g_count;
__device__ unsigned g_gen;

// ---------------- math helpers ----------------
__device__ __forceinline__ float softplus_(float r) {
    return (r > 15.f) ? r : log1pf(expf(r));
}
__device__ __forceinline__ float sample_(float mu, float rho, float eps) {
    return mu + softplus_(rho) * eps;
}
__device__ __forceinline__ float sigmoid_(float x) {
    return __fdividef(1.f, 1.f + __expf(-x));
}
__device__ __forceinline__ float tanh_(float x) {
    return __fdividef(2.f, 1.f + __expf(-2.f * x)) - 1.f;
}

// ---------------- packed fp32x2 FMA ----------------
typedef unsigned long long ull;
__device__ __forceinline__ ull pack2_(float x, float y) {
    ull r; asm("mov.b64 %0, {%1, %2};" : "=l"(r) : "f"(x), "f"(y)); return r;
}
__device__ __forceinline__ void unpack2_(ull v, float& x, float& y) {
    asm("mov.b64 {%0, %1}, %2;" : "=f"(x), "=f"(y) : "l"(v));
}
__device__ __forceinline__ void ffma2_(ull& acc, ull a, ull b) {
    asm("fma.rn.f32x2 %0, %1, %2, %3;" : "=l"(acc) : "l"(a), "l"(b), "l"(acc));
}

extern "C" __global__ void bar_init_kernel() {
    g_count = 0;
    g_gen = 0;
}

// inner FFMA block: 16 cols, one k, weights from SMEM row wrow
__device__ __forceinline__ void fma_row_(ull* acc, const float* wrow, float hval) {
    ull hv2 = pack2_(hval, hval);
    const ulonglong2* wr = (const ulonglong2*)wrow;
    ulonglong2 w0 = wr[0], w1 = wr[1], w2 = wr[2], w3 = wr[3];
    ffma2_(acc[0], w0.x, hv2); ffma2_(acc[1], w0.y, hv2);
    ffma2_(acc[2], w1.x, hv2); ffma2_(acc[3], w1.y, hv2);
    ffma2_(acc[4], w2.x, hv2); ffma2_(acc[5], w2.y, hv2);
    ffma2_(acc[6], w3.x, hv2); ffma2_(acc[7], w3.y, hv2);
}

// ---------------- main persistent LSTM kernel ----------------
extern "C" __global__ void __launch_bounds__(NTHR, 1)
lstm_persistent(const float* __restrict__ x,
                const float* __restrict__ wih_mu, const float* __restrict__ wih_rho,
                const float* __restrict__ wih_eps,
                const float* __restrict__ whh_mu, const float* __restrict__ whh_rho,
                const float* __restrict__ whh_eps,
                const float* __restrict__ b_mu,   const float* __restrict__ b_rho,
                const float* __restrict__ b_eps,
                const float* __restrict__ lin_w,  const float* __restrict__ lin_b,
                float* __restrict__ out)
{
    extern __shared__ float sm[];
    float* w_hh_s = sm + WHH_OFF;
    float* w_ih_s = sm + WIH_OFF;
    float* bias_s = sm + BIAS_OFF;
    float* part_s = sm + PART_OFF;

    const int tid  = threadIdx.x;
    const int half = tid >> 8;           // 0: k[0,256)+epilogue, 1: k[256,512)+x
    const int b    = tid & 255;          // batch row
    const int cta  = blockIdx.x;
    const int j0   = cta * HCOLS;

    // ---- sample weights for our 16 gate columns into SMEM ----
    for (int idx = tid; idx < H_ * CPC; idx += NTHR) {
        int k = idx >> 4, cc = idx & 15;
        int col = (cc >> 2) * H_ + j0 + (cc & 3);
        int gi = k * G_ + col;
        w_hh_s[idx] = sample_(whh_mu[gi], whh_rho[gi], whh_eps[gi]);
    }
    for (int idx = tid; idx < D_ * CPC; idx += NTHR) {
        int d = idx >> 4, cc = idx & 15;
        int col = (cc >> 2) * H_ + j0 + (cc & 3);
        int gi = d * G_ + col;
        w_ih_s[idx] = sample_(wih_mu[gi], wih_rho[gi], wih_eps[gi]);
    }
    if (tid < CPC) {
        int col = (tid >> 2) * H_ + j0 + (tid & 3);
        bias_s[tid] = sample_(b_mu[col], b_rho[col], b_eps[col]);
    }
    // zero h buffer 0 for our columns
    if (half == 0) {
        #pragma unroll
        for (int jj = 0; jj < HCOLS; jj++)
            g_hT[(j0 + jj) * B_ + b] = 0.f;
    }

    float creg[HCOLS] = {0.f, 0.f, 0.f, 0.f};   // live in half0 threads

    ull acc[8];
    #pragma unroll
    for (int p = 0; p < 8; p++) acc[p] = 0ull;

    __syncthreads();   // w_ih_s ready for half1's prologue x-part

    // half1 prologue: x-projection for t=0
    if (half == 1) {
        const float4* xrow = (const float4*)(x + (size_t)b * (T_ * D_));
        #pragma unroll 4
        for (int d4 = 0; d4 < D_ / 4; d4++) {
            float4 xq = xrow[d4];
            fma_row_(acc, &w_ih_s[(d4 * 4 + 0) * CPC], xq.x);
            fma_row_(acc, &w_ih_s[(d4 * 4 + 1) * CPC], xq.y);
            fma_row_(acc, &w_ih_s[(d4 * 4 + 2) * CPC], xq.z);
            fma_row_(acc, &w_ih_s[(d4 * 4 + 3) * CPC], xq.w);
        }
    }

    // initial grid sync (h zeros + weights visible everywhere)
    __syncthreads();
    if (tid == 0) {
        __threadfence();
        unsigned t0 = atomicAdd(&g_count, 1u);
        if (t0 == NCTA - 1) { g_count = 0; __threadfence(); atomicExch(&g_gen, 1u); }
        else {
            unsigned g;
            do { asm volatile("ld.global.cg.u32 %0, [%1];" : "=r"(g) : "l"(&g_gen)); 
                 if (g >= 1u) break; __nanosleep(32); } while (1);
        }
        __threadfence();
    }
    __syncthreads();

    const int kbase = half * KHALF;

    #pragma unroll 1
    for (int t = 0; t < T_; t++) {
        const int cur = t & 1, nxt = cur ^ 1;

        // ---- h-part over our k range, software pipelined, .cg loads ----
        const float* hbase = g_hT + cur * (H_ * B_) + (size_t)kbase * B_ + b;
        float hv[8], hn[8];
        #pragma unroll
        for (int u = 0; u < 8; u++) hv[u] = __ldcg(&hbase[u * B_]);

        #pragma unroll 1
        for (int k = 0; k < KHALF; k += 8) {
            const float* nb = hbase + (k + 8) * B_;   // padded: safe at the end
            #pragma unroll
            for (int u = 0; u < 8; u++) hn[u] = __ldcg(&nb[u * B_]);
            #pragma unroll
            for (int u = 0; u < 8; u++)
                fma_row_(acc, &w_hh_s[(kbase + k + u) * CPC], hv[u]);
            #pragma unroll
            for (int u = 0; u < 8; u++) hv[u] = hn[u];
        }

        // ---- half1 publishes partial (x(t) + h-high), resets acc ----
        if (half == 1) {
            ulonglong2* pr = (ulonglong2*)&part_s[b * PART_STRIDE];  // 16B aligned
            pr[0] = make_ulonglong2(acc[0], acc[1]);
            pr[1] = make_ulonglong2(acc[2], acc[3]);
            pr[2] = make_ulonglong2(acc[4], acc[5]);
            pr[3] = make_ulonglong2(acc[6], acc[7]);
            #pragma unroll
            for (int p = 0; p < 8; p++) acc[p] = 0ull;
        }
        __syncthreads();

        // ---- half0 epilogue: combine, gates, write h_{t+1} ----
        if (half == 0) {
            float ga[16];
            #pragma unroll
            for (int p = 0; p < 8; p++) unpack2_(acc[p], ga[2 * p], ga[2 * p + 1]);
            const float4* pf = (const float4*)&part_s[b * PART_STRIDE];
            const float4* bf = (const float4*)bias_s;
            #pragma unroll
            for (int q = 0; q < 4; q++) {
                float4 pv = pf[q], bv = bf[q];
                ga[4 * q + 0] += pv.x + bv.x;
                ga[4 * q + 1] += pv.y + bv.y;
                ga[4 * q + 2] += pv.z + bv.z;
                ga[4 * q + 3] += pv.w + bv.w;
            }
            float* hout = g_hT + nxt * (H_ * B_);
            #pragma unroll
            for (int jj = 0; jj < HCOLS; jj++) {
                float iv = sigmoid_(ga[jj]);
                float fv = sigmoid_(ga[4 + jj]);
                float gv = tanh_(ga[8 + jj]);
                float ov = sigmoid_(ga[12 + jj]);
                creg[jj] = fv * creg[jj] + iv * gv;
                float hval = ov * tanh_(creg[jj]);
                __stcg(&hout[(j0 + jj) * B_ + b], hval);
            }
            #pragma unroll
            for (int p = 0; p < 8; p++) acc[p] = 0ull;
        }
        __syncthreads();   // all h_{t+1} stores issued CTA-wide

        // ---- barrier arrive (tid0), x-part for t+1 (half1) overlaps poll ----
        if (tid == 0) {
            __threadfence();
            unsigned a = atomicAdd(&g_count, 1u);
            if (a == NCTA - 1) {
                g_count = 0;
                __threadfence();
                atomicExch(&g_gen, (unsigned)(t + 2));
            }
        }
        if (half == 1 && t + 1 < T_) {
            const float4* xrow =
                (const float4*)(x + (size_t)b * (T_ * D_) + (size_t)(t + 1) * D_);
            #pragma unroll 4
            for (int d4 = 0; d4 < D_ / 4; d4++) {
                float4 xq = xrow[d4];
                fma_row_(acc, &w_ih_s[(d4 * 4 + 0) * CPC], xq.x);
                fma_row_(acc, &w_ih_s[(d4 * 4 + 1) * CPC], xq.y);
                fma_row_(acc, &w_ih_s[(d4 * 4 + 2) * CPC], xq.z);
                fma_row_(acc, &w_ih_s[(d4 * 4 + 3) * CPC], xq.w);
            }
        }
        if (tid == 0) {
            unsigned target = (unsigned)(t + 2);
            unsigned g;
            do { asm volatile("ld.global.cg.u32 %0, [%1];" : "=r"(g) : "l"(&g_gen));
                 if (g >= target) break; __nanosleep(32); } while (1);
            __threadfence();
        }
        __syncthreads();
    }

    // After t=511, h_last sits in buffer 0.
    if (cta == 0 && half == 0) {
        float s = 0.f;
        #pragma unroll 4
        for (int j = 0; j < H_; j++)
            s += __ldcg(&g_hT[j * B_ + b]) * __ldg(&lin_w[j]);
        out[b] = s + __ldg(&lin_b[0]);
    }
}

// ---------------- launch ----------------
extern "C" void kernel_launch(void* const* d_in, const int* in_sizes, int n_in,
                              void* d_out, int out_size)
{
    const float* x       = (const float*)d_in[0];
    const float* wih_mu  = (const float*)d_in[1];
    const float* wih_rho = (const float*)d_in[2];
    const float* wih_eps = (const float*)d_in[3];
    const float* whh_mu  = (const float*)d_in[4];
    const float* whh_rho = (const float*)d_in[5];
    const float* whh_eps = (const float*)d_in[6];
    const float* b_mu    = (const float*)d_in[7];
    const float* b_rho   = (const float*)d_in[8];
    const float* b_eps   = (const float*)d_in[9];
    const float* lin_w   = (const float*)d_in[10];
    const float* lin_b   = (const float*)d_in[11];
    float* out = (float*)d_out;

    static int smem_set = 0;
    if (!smem_set) {
        cudaFuncSetAttribute(lstm_persistent,
                             cudaFuncAttributeMaxDynamicSharedMemorySize, SMEM_BYTES);
        smem_set = 1;
    }

    bar_init_kernel<<<1, 1>>>();
    lstm_persistent<<<NCTA, NTHR, SMEM_BYTES>>>(x,
                                    wih_mu, wih_rho, wih_eps,
                                    whh_mu, whh_rho, whh_eps,
                                    b_mu, b_rho, b_eps,
                                    lin_w, lin_b, out);
}

// round 5
// speedup vs baseline: 2.1080x; 1.8318x over previous
#include <cuda_runtime.h>
#include <cuda_bf16.h>
#include <cstdint>

// ---------------- problem constants ----------------
#define B_ 256
#define T_ 512
#define D_ 64
#define H_ 512
#define G_ 2048
#define NCTA 64
#define NTHR 256
#define HC 8              // h-columns per CTA (32 gate cols = 4 gates x 8)
#define NKC 9             // K chunks of 64: 8 for h + 1 for x
#define BROW 1168         // padded B row bytes (9*128 + 16)
#define BPLANE (32 * BROW)

// ---------------- dynamic SMEM layout (bytes) ----------------
#define SM_MB0 0
#define SM_MB1 8
#define SM_BIAS 64
#define SM_A 1024                       // 2 bufs x 2 planes x 32768 = 131072
#define SM_B (SM_A + 131072)            // 2 planes x 37376
#define SMEM_BYTES (SM_B + 2 * BPLANE)  // 206848

// ---------------- persistent device state ----------------
// h in K-blocked swizzled layout: [buf][plane][kc][row][64 cols (swizzled bytes)]
__device__ __align__(128) __nv_bfloat16 g_hA[2][2][8][256][64];
// x in per-step K-blocked swizzled layout: [plane][t][row][64]
__device__ __align__(128) __nv_bfloat16 g_xA[2][T_][256][64];
__device__ unsigned g_count, g_gen;

// ---------------- math helpers ----------------
__device__ __forceinline__ float softplus_(float r) {
    return (r > 15.f) ? r : log1pf(expf(r));
}
__device__ __forceinline__ float sample_(float mu, float rho, float eps) {
    return mu + softplus_(rho) * eps;
}
__device__ __forceinline__ float sigmoid_(float x) {
    return __fdividef(1.f, 1.f + __expf(-x));
}
__device__ __forceinline__ float tanh_(float x) {
    return __fdividef(2.f, 1.f + __expf(-2.f * x)) - 1.f;
}

// ---------------- PTX helpers ----------------
__device__ __forceinline__ uint32_t smem_u32_(const void* p) {
    uint32_t a;
    asm("{ .reg .u64 t; cvta.to.shared.u64 t, %1; cvt.u32.u64 %0, t; }"
        : "=r"(a) : "l"(p));
    return a;
}
__device__ __forceinline__ void mbar_init_(uint32_t a, uint32_t cnt) {
    asm volatile("mbarrier.init.shared.b64 [%0], %1;" :: "r"(a), "r"(cnt) : "memory");
}
__device__ __forceinline__ void mbar_inval_(uint32_t a) {
    asm volatile("mbarrier.inval.shared.b64 [%0];" :: "r"(a) : "memory");
}
__device__ __forceinline__ void mbar_expect_tx_(uint32_t a, uint32_t bytes) {
    asm volatile("mbarrier.arrive.expect_tx.shared.b64 _, [%0], %1;"
                 :: "r"(a), "r"(bytes) : "memory");
}
__device__ __forceinline__ void mbar_wait_(uint32_t a, uint32_t parity) {
    uint32_t done;
    asm volatile(
        "{\n\t.reg .pred p;\n\t"
        "mbarrier.try_wait.parity.acquire.cta.shared::cta.b64 p, [%1], %2;\n\t"
        "selp.b32 %0, 1, 0, p;\n\t}"
        : "=r"(done) : "r"(a), "r"(parity) : "memory");
    if (!done) {
        asm volatile(
            "{\n\t.reg .pred P1;\n\t"
            "W_%=:\n\t"
            "mbarrier.try_wait.parity.acquire.cta.shared::cta.b64 P1, [%0], %1, 0x989680;\n\t"
            "@P1 bra.uni D_%=;\n\t"
            "bra.uni W_%=;\n\t"
            "D_%=:\n\t}"
            :: "r"(a), "r"(parity) : "memory");
    }
}
__device__ __forceinline__ void bulk_g2s_(uint32_t dst, const void* src,
                                          uint32_t bytes, uint32_t mbar) {
    asm volatile(
        "cp.async.bulk.shared::cluster.global.mbarrier::complete_tx::bytes "
        "[%0], [%1], %2, [%3];"
        :: "r"(dst), "l"(src), "r"(bytes), "r"(mbar) : "memory");
}

#define LDM4(R, A) \
    asm volatile("ldmatrix.sync.aligned.m8n8.x4.shared.b16 {%0,%1,%2,%3}, [%4];" \
        : "=r"((R)[0]), "=r"((R)[1]), "=r"((R)[2]), "=r"((R)[3]) : "r"(A))

#define MMA(Cf, Af, Bf0, Bf1) \
    asm volatile("mma.sync.aligned.m16n8k16.row.col.f32.bf16.bf16.f32 " \
        "{%0,%1,%2,%3}, {%4,%5,%6,%7}, {%8,%9}, {%0,%1,%2,%3};" \
        : "+f"((Cf)[0]), "+f"((Cf)[1]), "+f"((Cf)[2]), "+f"((Cf)[3]) \
        : "r"((Af)[0]), "r"((Af)[1]), "r"((Af)[2]), "r"((Af)[3]), \
          "r"(Bf0), "r"(Bf1))

extern "C" __global__ void bar_init_kernel() {
    g_count = 0;
    g_gen = 0;
}

// ---------------- grid barrier ----------------
__device__ __forceinline__ void grid_sync_(unsigned target) {
    __syncthreads();
    if (threadIdx.x == 0) {
        __threadfence();
        unsigned a = atomicAdd(&g_count, 1u);
        if (a == NCTA - 1) {
            g_count = 0;
            __threadfence();
            atomicExch(&g_gen, target);
        } else {
            unsigned g;
            do {
                asm volatile("ld.global.cg.u32 %0, [%1];" : "=r"(g) : "l"(&g_gen));
                if (g >= target) break;
                __nanosleep(32);
            } while (1);
        }
        __threadfence();
    }
    __syncthreads();
}

// issue both planes of one K-chunk as bulk copies (tid0 only)
__device__ __forceinline__ void issue_chunk_(uint32_t sbase, int buf, int kc,
                                             int t, uint32_t mbar) {
    mbar_expect_tx_(mbar, 65536u);
    #pragma unroll
    for (int plane = 0; plane < 2; plane++) {
        const char* src;
        if (kc < 8)
            src = (const char*)g_hA +
                  ((((size_t)(t & 1)) * 2 + plane) * 8 + kc) * 32768;
        else
            src = (const char*)g_xA + ((size_t)plane * T_ + t) * 32768;
        uint32_t dst = sbase + SM_A + buf * 65536 + plane * 32768;
        bulk_g2s_(dst, src, 32768u, mbar);
    }
}

// ---------------- main persistent kernel ----------------
extern "C" __global__ void __launch_bounds__(NTHR, 1)
lstm_hmma(const float* __restrict__ x,
          const float* __restrict__ wih_mu, const float* __restrict__ wih_rho,
          const float* __restrict__ wih_eps,
          const float* __restrict__ whh_mu, const float* __restrict__ whh_rho,
          const float* __restrict__ whh_eps,
          const float* __restrict__ b_mu,   const float* __restrict__ b_rho,
          const float* __restrict__ b_eps,
          const float* __restrict__ lin_w,  const float* __restrict__ lin_b,
          float* __restrict__ out)
{
    extern __shared__ char smem[];
    const uint32_t sbase = smem_u32_(smem);
    const uint32_t mbar[2] = { sbase + SM_MB0, sbase + SM_MB1 };
    float* bias_s = (float*)(smem + SM_BIAS);

    const int tid  = threadIdx.x;
    const int lane = tid & 31;
    const int w    = tid >> 5;
    const int cta  = blockIdx.x;
    const int j0   = cta * HC;

    if (tid == 0) { mbar_init_(mbar[0], 1); mbar_init_(mbar[1], 1); }

    // ---- sample W into SMEM B planes: rows n (32), cols k (576), padded ----
    for (int idx = tid; idx < 32 * 576; idx += NTHR) {
        int n = idx / 576, k = idx - n * 576;
        int col = (n >> 3) * H_ + j0 + (n & 7);
        float wv;
        if (k < 512) {
            int gi = k * G_ + col;
            wv = sample_(whh_mu[gi], whh_rho[gi], whh_eps[gi]);
        } else {
            int gi = (k - 512) * G_ + col;
            wv = sample_(wih_mu[gi], wih_rho[gi], wih_eps[gi]);
        }
        __nv_bfloat16 hi = __float2bfloat16(wv);
        __nv_bfloat16 lo = __float2bfloat16(wv - __bfloat162float(hi));
        *(__nv_bfloat16*)(smem + SM_B + 0 * BPLANE + n * BROW + k * 2) = hi;
        *(__nv_bfloat16*)(smem + SM_B + 1 * BPLANE + n * BROW + k * 2) = lo;
    }
    if (tid < 32) {
        int col = (tid >> 3) * H_ + j0 + (tid & 7);
        bias_s[tid] = sample_(b_mu[col], b_rho[col], b_eps[col]);
    }

    // ---- build swizzled x planes + zero h buf0 (grid-wide) ----
    {
        const int gtid = cta * NTHR + tid;
        const int gn = NCTA * NTHR;
        for (int i = gtid; i < B_ * T_ * D_; i += gn) {
            int d = i & 63, r = i >> 6;
            int t = r & 511, b = r >> 9;            // x is [b][t][d]
            float v = __ldg(&x[i]);
            __nv_bfloat16 hi = __float2bfloat16(v);
            __nv_bfloat16 lo = __float2bfloat16(v - __bfloat162float(hi));
            uint32_t off = ((uint32_t)t * 256 + (uint32_t)b) * 128 +
                           (((uint32_t)d * 2) ^ (((uint32_t)b & 7) << 4));
            *(__nv_bfloat16*)((char*)g_xA + off) = hi;
            *(__nv_bfloat16*)((char*)g_xA + (size_t)T_ * 32768 + off) = lo;
        }
        uint32_t* hz = (uint32_t*)g_hA;             // buf0, both planes: 131072 u32
        for (int i = gtid; i < 131072; i += gn) hz[i] = 0u;
    }

    grid_sync_(1);

    // ---- per-thread fragment address precompute ----
    const uint32_t akey = ((uint32_t)(lane & 7)) << 4;
    uint32_t arow[2];
    arow[0] = (uint32_t)(w * 32 + (lane & 15)) * 128;
    arow[1] = arow[0] + 16 * 128;
    uint32_t asw[4];
    #pragma unroll
    for (int ks = 0; ks < 4; ks++)
        asw[ks] = ((uint32_t)(ks * 32 + ((lane >> 4) * 16))) ^ akey;
    uint32_t bo[2];
    {
        uint32_t nrow = (uint32_t)(((lane >> 4) << 3) + (lane & 7));
        bo[0] = nrow * BROW + ((uint32_t)((lane >> 3) & 1)) * 16;
        bo[1] = bo[0] + 16 * BROW;
    }

    float cst[4][2];
    #pragma unroll
    for (int rr = 0; rr < 4; rr++) { cst[rr][0] = 0.f; cst[rr][1] = 0.f; }

    int ph[2] = {0, 0};
    unsigned epoch = 2;

    const int jj0 = (lane & 3) * 2;
    const int kc0 = j0 >> 6;
    const int u0  = (j0 & 63) + jj0;

    // ---------------- time loop ----------------
    #pragma unroll 1
    for (int t = 0; t < T_; t++) {
        float C[2][4][4];
        #pragma unroll
        for (int mt = 0; mt < 2; mt++)
            #pragma unroll
            for (int n = 0; n < 4; n++)
                #pragma unroll
                for (int q = 0; q < 4; q++) C[mt][n][q] = 0.f;

        if (tid == 0) {
            issue_chunk_(sbase, 0, 0, t, mbar[0]);
            issue_chunk_(sbase, 1, 1, t, mbar[1]);
        }

        #pragma unroll 1
        for (int c = 0; c < NKC; c++) {
            const int buf = c & 1;
            mbar_wait_(mbar[buf], (uint32_t)ph[buf]);
            ph[buf] ^= 1;

            const uint32_t a0 = sbase + SM_A + buf * 65536;
            const uint32_t bb = sbase + SM_B + (uint32_t)c * 128;

            #pragma unroll
            for (int ks = 0; ks < 4; ks++) {
                uint32_t Ah[2][4], Al[2][4], Bh[4][2], Bl[4][2];
                #pragma unroll
                for (int mt = 0; mt < 2; mt++) {
                    LDM4(Ah[mt], a0 + arow[mt] + asw[ks]);
                    LDM4(Al[mt], a0 + 32768 + arow[mt] + asw[ks]);
                }
                #pragma unroll
                for (int p = 0; p < 2; p++) {
                    uint32_t r_[4];
                    LDM4(r_, bb + bo[p] + ks * 32);
                    Bh[2 * p][0] = r_[0]; Bh[2 * p][1] = r_[1];
                    Bh[2 * p + 1][0] = r_[2]; Bh[2 * p + 1][1] = r_[3];
                    LDM4(r_, bb + BPLANE + bo[p] + ks * 32);
                    Bl[2 * p][0] = r_[0]; Bl[2 * p][1] = r_[1];
                    Bl[2 * p + 1][0] = r_[2]; Bl[2 * p + 1][1] = r_[3];
                }
                #pragma unroll
                for (int mt = 0; mt < 2; mt++)
                    #pragma unroll
                    for (int n = 0; n < 4; n++) {
                        MMA(C[mt][n], Ah[mt], Bh[n][0], Bh[n][1]);
                        MMA(C[mt][n], Ah[mt], Bl[n][0], Bl[n][1]);
                        MMA(C[mt][n], Al[mt], Bh[n][0], Bh[n][1]);
                    }
            }
            __syncthreads();
            if (c <= NKC - 3 && tid == 0)
                issue_chunk_(sbase, buf, c + 2, t, mbar[buf]);
        }

        // ---- epilogue: gates in registers, write swizzled h ----
        {
            const int nbuf = (t + 1) & 1;
            char* hb0 = (char*)g_hA + (((size_t)nbuf * 2 + 0) * 8 + kc0) * 32768;
            char* hb1 = hb0 + 8 * 32768;
            #pragma unroll
            for (int rr = 0; rr < 4; rr++) {
                int r = w * 32 + (lane >> 2) + rr * 8;
                int mt = rr >> 1, ci = (rr & 1) * 2;
                float hv[2];
                #pragma unroll
                for (int q = 0; q < 2; q++) {
                    float iv = sigmoid_(C[mt][0][ci + q] + bias_s[jj0 + q]);
                    float fv = sigmoid_(C[mt][1][ci + q] + bias_s[8 + jj0 + q]);
                    float gv = tanh_   (C[mt][2][ci + q] + bias_s[16 + jj0 + q]);
                    float ov = sigmoid_(C[mt][3][ci + q] + bias_s[24 + jj0 + q]);
                    cst[rr][q] = fv * cst[rr][q] + iv * gv;
                    hv[q] = ov * tanh_(cst[rr][q]);
                }
                __nv_bfloat16 h0 = __float2bfloat16(hv[0]);
                __nv_bfloat16 h1 = __float2bfloat16(hv[1]);
                __nv_bfloat16 l0 = __float2bfloat16(hv[0] - __bfloat162float(h0));
                __nv_bfloat16 l1 = __float2bfloat16(hv[1] - __bfloat162float(h1));
                uint32_t off = (uint32_t)r * 128 +
                               (((uint32_t)u0 * 2) ^ (((uint32_t)r & 7) << 4));
                *(uint32_t*)(hb0 + off) =
                    (uint32_t)__bfloat16_as_ushort(h0) |
                    ((uint32_t)__bfloat16_as_ushort(h1) << 16);
                *(uint32_t*)(hb1 + off) =
                    (uint32_t)__bfloat16_as_ushort(l0) |
                    ((uint32_t)__bfloat16_as_ushort(l1) << 16);
            }
        }

        grid_sync_(epoch++);
    }

    // ---- final linear: h_last in buf 0 ----
    if (cta == 0) {
        const int b = tid;
        float s = 0.f;
        #pragma unroll 4
        for (int j = 0; j < H_; j++) {
            uint32_t off = (((uint32_t)(j >> 6)) * 256 + (uint32_t)b) * 128 +
                           (((uint32_t)(j & 63) * 2) ^ (((uint32_t)b & 7) << 4));
            float hv = __bfloat162float(*(const __nv_bfloat16*)((char*)g_hA + off)) +
                       __bfloat162float(*(const __nv_bfloat16*)((char*)g_hA +
                                                                8 * 32768 + off));
            s += hv * __ldg(&lin_w[j]);
        }
        out[b] = s + __ldg(&lin_b[0]);
    }

    __syncthreads();
    if (tid == 0) { mbar_inval_(mbar[0]); mbar_inval_(mbar[1]); }
}

// ---------------- launch ----------------
extern "C" void kernel_launch(void* const* d_in, const int* in_sizes, int n_in,
                              void* d_out, int out_size)
{
    const float* x       = (const float*)d_in[0];
    const float* wih_mu  = (const float*)d_in[1];
    const float* wih_rho = (const float*)d_in[2];
    const float* wih_eps = (const float*)d_in[3];
    const float* whh_mu  = (const float*)d_in[4];
    const float* whh_rho = (const float*)d_in[5];
    const float* whh_eps = (const float*)d_in[6];
    const float* b_mu    = (const float*)d_in[7];
    const float* b_rho   = (const float*)d_in[8];
    const float* b_eps   = (const float*)d_in[9];
    const float* lin_w   = (const float*)d_in[10];
    const float* lin_b   = (const float*)d_in[11];
    float* out = (float*)d_out;

    static int inited = 0;
    if (!inited) {
        cudaFuncSetAttribute(lstm_hmma,
                             cudaFuncAttributeMaxDynamicSharedMemorySize, SMEM_BYTES);
        inited = 1;
    }

    bar_init_kernel<<<1, 1>>>();
    lstm_hmma<<<NCTA, NTHR, SMEM_BYTES>>>(x,
                                          wih_mu, wih_rho, wih_eps,
                                          whh_mu, whh_rho, whh_eps,
                                          b_mu, b_rho, b_eps,
                                          lin_w, lin_b, out);
}